// round 11
// baseline (speedup 1.0000x reference)
#include <cuda_runtime.h>
#include <cstdint>
#include <cstddef>

// Problem constants
#define B_Q   1024
#define D_DIM 256
#define N_TR  200000
#define N_CLS 1000
#define K_TOP 20
#define TEMP  20.0f

// GEMM tiling
#define NT_TILE 128                 // train rows per CTA
#define MT_TILE 64                  // query rows per m-block
#define PITCH   260                 // 256 + 4 pad -> conflict-free LDS.128
#define SMEM_BYTES ((NT_TILE + MT_TILE) * PITCH * 4)

// ---------------- device scratch (statically allocated; no cudaMalloc) ------
__device__ __align__(16) float g_q[B_Q * D_DIM];        // normalized queries
__device__ float g_txinv[N_TR];                          // 1/max(||t||,eps)
__device__ __align__(16) float g_sim[(size_t)B_Q * N_TR]; // 819 MB sim matrix
__device__ float g_topv[B_Q * K_TOP];
__device__ int   g_topi[B_Q * K_TOP];

// ---------------- packed f32x2 FMA ------------------------------------------
__device__ __forceinline__ void ffma2(unsigned long long& c,
                                      unsigned long long a,
                                      unsigned long long b) {
    asm("fma.rn.f32x2 %0, %1, %2, %0;" : "+l"(c) : "l"(a), "l"(b));
}

// ---------------- kernel 1: q = l2norm((x-mean)*inv_std) --------------------
__global__ void k_qnorm(const float* __restrict__ x,
                        const float* __restrict__ mean,
                        const float* __restrict__ inv_std) {
    __shared__ float red[8];
    __shared__ float s_den;
    const int b = blockIdx.x, d = threadIdx.x;
    float t = (x[b * D_DIM + d] - mean[d]) * inv_std[d];
    float ss = t * t;
    #pragma unroll
    for (int o = 16; o; o >>= 1) ss += __shfl_xor_sync(0xffffffffu, ss, o);
    if ((d & 31) == 0) red[d >> 5] = ss;
    __syncthreads();
    if (d == 0) {
        float s = 0.f;
        #pragma unroll
        for (int w = 0; w < 8; w++) s += red[w];
        s_den = fmaxf(sqrtf(s), 1e-8f);
    }
    __syncthreads();
    g_q[b * D_DIM + d] = t / s_den;
}

// ---------------- kernel 2: per-row inverse L2 norm of train bank -----------
__global__ void k_txinv(const float* __restrict__ tx) {
    const int row  = blockIdx.x * 8 + (threadIdx.x >> 5);
    const int lane = threadIdx.x & 31;
    const float4* p = (const float4*)(tx + (size_t)row * D_DIM);
    float4 a = p[lane * 2];
    float4 c = p[lane * 2 + 1];
    float ss = a.x*a.x + a.y*a.y + a.z*a.z + a.w*a.w
             + c.x*c.x + c.y*c.y + c.z*c.z + c.w*c.w;
    #pragma unroll
    for (int o = 16; o; o >>= 1) ss += __shfl_xor_sync(0xffffffffu, ss, o);
    if (lane == 0) g_txinv[row] = 1.0f / fmaxf(sqrtf(ss), 1e-8f);
}

// ---------------- kernel 3: sim = q @ txn^T (fp32 via packed f32x2) ---------
__global__ void __launch_bounds__(256, 1) k_gemm(const float* __restrict__ tx) {
    extern __shared__ float sm[];
    float* txs = sm;                       // NT_TILE x PITCH
    float* qs  = sm + NT_TILE * PITCH;     // MT_TILE x PITCH

    const int n0  = blockIdx.x * NT_TILE;
    const int tid = threadIdx.x;

    // Load tx tile once, folding L2 normalization; zero-pad past N_TR.
    for (int idx = tid; idx < NT_TILE * 64; idx += 256) {
        const int r = idx >> 6, c4 = idx & 63;
        const int n = n0 + r;
        float4 v = make_float4(0.f, 0.f, 0.f, 0.f);
        if (n < N_TR) {
            v = __ldg((const float4*)(tx + (size_t)n * D_DIM) + c4);
            const float s = g_txinv[n];
            v.x *= s; v.y *= s; v.z *= s; v.w *= s;
        }
        *(float4*)(txs + r * PITCH + c4 * 4) = v;
    }
    __syncthreads();

    const int nt = tid & 31;   // n-group: warp lanes span all 32
    const int mt = tid >> 5;   // m-group: uniform within a warp (q broadcast)

    for (int mb = 0; mb < B_Q / MT_TILE; mb++) {
        for (int idx = tid; idx < MT_TILE * 64; idx += 256) {
            const int r = idx >> 6, c4 = idx & 63;
            *(float4*)(qs + r * PITCH + c4 * 4) =
                ((const float4*)(g_q + (mb * MT_TILE + r) * D_DIM))[c4];
        }
        __syncthreads();

        unsigned long long acc[8][4];
        #pragma unroll
        for (int i = 0; i < 8; i++)
            #pragma unroll
            for (int j = 0; j < 4; j++) acc[i][j] = 0ULL;  // bits(+0,+0)

        #pragma unroll 2
        for (int k4 = 0; k4 < 64; k4++) {
            ulonglong2 bf[4], af[8];
            #pragma unroll
            for (int j = 0; j < 4; j++)
                bf[j] = *(const ulonglong2*)(txs + (nt + 32 * j) * PITCH + k4 * 4);
            #pragma unroll
            for (int i = 0; i < 8; i++)
                af[i] = *(const ulonglong2*)(qs + (mt * 8 + i) * PITCH + k4 * 4);
            #pragma unroll
            for (int i = 0; i < 8; i++)
                #pragma unroll
                for (int j = 0; j < 4; j++)
                    ffma2(acc[i][j], af[i].x, bf[j].x);
            #pragma unroll
            for (int i = 0; i < 8; i++)
                #pragma unroll
                for (int j = 0; j < 4; j++)
                    ffma2(acc[i][j], af[i].y, bf[j].y);
        }

        #pragma unroll
        for (int i = 0; i < 8; i++) {
            const int m = mb * MT_TILE + mt * 8 + i;
            float* orow = g_sim + (size_t)m * N_TR + n0;
            #pragma unroll
            for (int j = 0; j < 4; j++) {
                const int n = nt + 32 * j;
                if (n0 + n < N_TR) {
                    float lo, hi;
                    asm("mov.b64 {%0,%1}, %2;" : "=f"(lo), "=f"(hi) : "l"(acc[i][j]));
                    orow[n] = lo + hi;   // even-k + odd-k partial sums
                }
            }
        }
        __syncthreads();
    }
}

// ---------------- kernel 4: per-row top-20 of 200000 ------------------------
__device__ __forceinline__ void tk_rescan(const float* sv, int base,
                                          float& vmin, int& pmin) {
    float m = sv[base]; int p = base;
    #pragma unroll
    for (int j = 1; j < K_TOP; j++) {
        const float w = sv[base + j];
        if (w < m) { m = w; p = base + j; }
    }
    vmin = m; pmin = p;
}

__device__ __forceinline__ void tk_insert4(float4 v, int i4,
                                           float* sv, int* si, int base,
                                           float& vmin, int& pmin) {
    if (v.x > vmin) { sv[pmin] = v.x; si[pmin] = i4 + 0; tk_rescan(sv, base, vmin, pmin); }
    if (v.y > vmin) { sv[pmin] = v.y; si[pmin] = i4 + 1; tk_rescan(sv, base, vmin, pmin); }
    if (v.z > vmin) { sv[pmin] = v.z; si[pmin] = i4 + 2; tk_rescan(sv, base, vmin, pmin); }
    if (v.w > vmin) { sv[pmin] = v.w; si[pmin] = i4 + 3; tk_rescan(sv, base, vmin, pmin); }
}

__device__ __forceinline__ float max4(float4 v) {
    return fmaxf(fmaxf(v.x, v.y), fmaxf(v.z, v.w));
}

__global__ void __launch_bounds__(256) k_topk() {
    __shared__ float sv[256 * K_TOP];
    __shared__ int   si[256 * K_TOP];
    __shared__ float rv[8];
    __shared__ int   rp[8];
    const int b    = blockIdx.x;
    const int tid  = threadIdx.x;
    const int base = tid * K_TOP;

    #pragma unroll
    for (int j = 0; j < K_TOP; j++) { sv[base + j] = -2.0f; si[base + j] = 0; }
    float vmin = -2.0f; int pmin = base;

    const float4* row4 = (const float4*)(g_sim + (size_t)b * N_TR);
    const int F4 = N_TR / 4;                 // 50000 float4s per row

    // Main scan: 16 elements per iteration behind one max-tree compare.
    // 4 independent coalesced LDG.128 per thread -> MLP=4, DRAM-latency hidden.
    int i = tid;
    for (; i + 768 < F4; i += 1024) {
        const float4 v0 = row4[i];
        const float4 v1 = row4[i + 256];
        const float4 v2 = row4[i + 512];
        const float4 v3 = row4[i + 768];
        const float m0 = max4(v0), m1 = max4(v1), m2 = max4(v2), m3 = max4(v3);
        const float mm = fmaxf(fmaxf(m0, m1), fmaxf(m2, m3));
        if (mm > vmin) {
            if (m0 > vmin) tk_insert4(v0, (i      ) << 2, sv, si, base, vmin, pmin);
            if (m1 > vmin) tk_insert4(v1, (i + 256) << 2, sv, si, base, vmin, pmin);
            if (m2 > vmin) tk_insert4(v2, (i + 512) << 2, sv, si, base, vmin, pmin);
            if (m3 > vmin) tk_insert4(v3, (i + 768) << 2, sv, si, base, vmin, pmin);
        }
    }
    // Tail (remaining < 1024 float4s)
    for (; i < F4; i += 256) {
        const float4 v = row4[i];
        if (max4(v) > vmin) tk_insert4(v, i << 2, sv, si, base, vmin, pmin);
    }
    __syncthreads();

    // Final exact top-20 across 256 thread-local lists.
    const int lane = tid & 31, wid = tid >> 5;
    for (int r = 0; r < K_TOP; r++) {
        float lv = -3.0f; int lp = base;
        #pragma unroll
        for (int j = 0; j < K_TOP; j++) {
            const float w = sv[base + j];
            if (w > lv) { lv = w; lp = base + j; }
        }
        #pragma unroll
        for (int o = 16; o > 0; o >>= 1) {
            const float ov = __shfl_down_sync(0xffffffffu, lv, o);
            const int   op = __shfl_down_sync(0xffffffffu, lp, o);
            if (ov > lv) { lv = ov; lp = op; }
        }
        if (lane == 0) { rv[wid] = lv; rp[wid] = lp; }
        __syncthreads();
        if (tid == 0) {
            float gv = rv[0]; int gp = rp[0];
            #pragma unroll
            for (int w = 1; w < 8; w++)
                if (rv[w] > gv) { gv = rv[w]; gp = rp[w]; }
            g_topv[b * K_TOP + r] = gv;
            g_topi[b * K_TOP + r] = si[gp];
            sv[gp] = -3.0f;   // consume
        }
        __syncthreads();
    }
}

// ---------------- kernel 5: zero row + softmax-weighted label scatter -------
// train_y arrives as int32 (jax x64-disabled downcasts the reference's int64).
__global__ void k_out(const int* __restrict__ ty, float* __restrict__ out) {
    const int b = blockIdx.x;
    float* row = out + b * N_CLS;
    for (int i = threadIdx.x; i < N_CLS; i += 256) row[i] = 0.0f;
    __syncthreads();
    if (threadIdx.x < 32) {
        const int j = threadIdx.x;
        const float v = (j < K_TOP) ? g_topv[b * K_TOP + j] : -1e30f;
        float mx = v;
        #pragma unroll
        for (int o = 16; o; o >>= 1) mx = fmaxf(mx, __shfl_xor_sync(0xffffffffu, mx, o));
        const float e = (j < K_TOP) ? expf((v - mx) * TEMP) : 0.0f;
        float s = e;
        #pragma unroll
        for (int o = 16; o; o >>= 1) s += __shfl_xor_sync(0xffffffffu, s, o);
        if (j < K_TOP) {
            const int lab = ty[g_topi[b * K_TOP + j]];
            atomicAdd(row + lab, e / s);
        }
    }
}

// ---------------- launch -----------------------------------------------------
extern "C" void kernel_launch(void* const* d_in, const int* in_sizes, int n_in,
                              void* d_out, int out_size) {
    (void)in_sizes; (void)n_in; (void)out_size;
    const float* x       = (const float*)d_in[0];
    const float* mean    = (const float*)d_in[1];
    const float* inv_std = (const float*)d_in[2];
    const float* tx      = (const float*)d_in[3];
    const int*   ty      = (const int*)d_in[4];
    float* out = (float*)d_out;

    cudaFuncSetAttribute(k_gemm, cudaFuncAttributeMaxDynamicSharedMemorySize,
                         SMEM_BYTES);

    k_qnorm<<<B_Q, 256>>>(x, mean, inv_std);
    k_txinv<<<N_TR / 8, 256>>>(tx);
    k_gemm<<<(N_TR + NT_TILE - 1) / NT_TILE, 256, SMEM_BYTES>>>(tx);
    k_topk<<<B_Q, 256>>>();
    k_out<<<B_Q, 256>>>(ty, out);
}

// round 12
// speedup vs baseline: 1.2058x; 1.2058x over previous
#include <cuda_runtime.h>
#include <cstdint>
#include <cstddef>

// Problem constants
#define B_Q   1024
#define D_DIM 256
#define N_TR  200000
#define N_CLS 1000
#define K_TOP 20
#define TEMP  20.0f

// GEMM tiling
#define NT_TILE 128                 // train rows per CTA
#define MT_TILE 64                  // query rows per m-block
#define PITCH   260                 // 256 + 4 pad -> conflict-free LDS.128
#define SMEM_BYTES ((NT_TILE + MT_TILE) * PITCH * 4)
#define NBLK  ((N_TR + NT_TILE - 1) / NT_TILE)   // 1563 n-blocks

// ---------------- device scratch (statically allocated; no cudaMalloc) ------
__device__ __align__(16) float g_q[B_Q * D_DIM];          // normalized queries
__device__ float g_txinv[N_TR];                            // 1/max(||t||,eps)
__device__ __align__(16) float g_sim[(size_t)B_Q * N_TR];  // 819 MB sim matrix
__device__ float g_blkmax[(size_t)B_Q * NBLK];             // per-row block maxes
__device__ float g_topv[B_Q * K_TOP];
__device__ int   g_topi[B_Q * K_TOP];

// ---------------- packed f32x2 FMA ------------------------------------------
__device__ __forceinline__ void ffma2(unsigned long long& c,
                                      unsigned long long a,
                                      unsigned long long b) {
    asm("fma.rn.f32x2 %0, %1, %2, %0;" : "+l"(c) : "l"(a), "l"(b));
}

// ---------------- kernel 1: q = l2norm((x-mean)*inv_std) --------------------
__global__ void k_qnorm(const float* __restrict__ x,
                        const float* __restrict__ mean,
                        const float* __restrict__ inv_std) {
    __shared__ float red[8];
    __shared__ float s_den;
    const int b = blockIdx.x, d = threadIdx.x;
    float t = (x[b * D_DIM + d] - mean[d]) * inv_std[d];
    float ss = t * t;
    #pragma unroll
    for (int o = 16; o; o >>= 1) ss += __shfl_xor_sync(0xffffffffu, ss, o);
    if ((d & 31) == 0) red[d >> 5] = ss;
    __syncthreads();
    if (d == 0) {
        float s = 0.f;
        #pragma unroll
        for (int w = 0; w < 8; w++) s += red[w];
        s_den = fmaxf(sqrtf(s), 1e-8f);
    }
    __syncthreads();
    g_q[b * D_DIM + d] = t / s_den;
}

// ---------------- kernel 2: per-row inverse L2 norm of train bank -----------
__global__ void k_txinv(const float* __restrict__ tx) {
    const int row  = blockIdx.x * 8 + (threadIdx.x >> 5);
    const int lane = threadIdx.x & 31;
    const float4* p = (const float4*)(tx + (size_t)row * D_DIM);
    float4 a = p[lane * 2];
    float4 c = p[lane * 2 + 1];
    float ss = a.x*a.x + a.y*a.y + a.z*a.z + a.w*a.w
             + c.x*c.x + c.y*c.y + c.z*c.z + c.w*c.w;
    #pragma unroll
    for (int o = 16; o; o >>= 1) ss += __shfl_xor_sync(0xffffffffu, ss, o);
    if (lane == 0) g_txinv[row] = 1.0f / fmaxf(sqrtf(ss), 1e-8f);
}

// ---------------- kernel 3: sim = q @ txn^T (fp32 via packed f32x2) ---------
// Epilogue additionally emits the per-(row, n-block) max into g_blkmax for
// the pruned top-k pass. Padded lanes (n >= N_TR) excluded from the max.
__global__ void __launch_bounds__(256, 1) k_gemm(const float* __restrict__ tx) {
    extern __shared__ float sm[];
    float* txs = sm;                       // NT_TILE x PITCH
    float* qs  = sm + NT_TILE * PITCH;     // MT_TILE x PITCH

    const int n0  = blockIdx.x * NT_TILE;
    const int tid = threadIdx.x;

    // Load tx tile once, folding L2 normalization; zero-pad past N_TR.
    for (int idx = tid; idx < NT_TILE * 64; idx += 256) {
        const int r = idx >> 6, c4 = idx & 63;
        const int n = n0 + r;
        float4 v = make_float4(0.f, 0.f, 0.f, 0.f);
        if (n < N_TR) {
            v = __ldg((const float4*)(tx + (size_t)n * D_DIM) + c4);
            const float s = g_txinv[n];
            v.x *= s; v.y *= s; v.z *= s; v.w *= s;
        }
        *(float4*)(txs + r * PITCH + c4 * 4) = v;
    }
    __syncthreads();

    const int nt = tid & 31;   // n-group: warp lanes span all 32
    const int mt = tid >> 5;   // m-group: uniform within a warp (q broadcast)

    for (int mb = 0; mb < B_Q / MT_TILE; mb++) {
        for (int idx = tid; idx < MT_TILE * 64; idx += 256) {
            const int r = idx >> 6, c4 = idx & 63;
            *(float4*)(qs + r * PITCH + c4 * 4) =
                ((const float4*)(g_q + (mb * MT_TILE + r) * D_DIM))[c4];
        }
        __syncthreads();

        unsigned long long acc[8][4];
        #pragma unroll
        for (int i = 0; i < 8; i++)
            #pragma unroll
            for (int j = 0; j < 4; j++) acc[i][j] = 0ULL;  // bits(+0,+0)

        #pragma unroll 2
        for (int k4 = 0; k4 < 64; k4++) {
            ulonglong2 bf[4], af[8];
            #pragma unroll
            for (int j = 0; j < 4; j++)
                bf[j] = *(const ulonglong2*)(txs + (nt + 32 * j) * PITCH + k4 * 4);
            #pragma unroll
            for (int i = 0; i < 8; i++)
                af[i] = *(const ulonglong2*)(qs + (mt * 8 + i) * PITCH + k4 * 4);
            #pragma unroll
            for (int i = 0; i < 8; i++)
                #pragma unroll
                for (int j = 0; j < 4; j++)
                    ffma2(acc[i][j], af[i].x, bf[j].x);
            #pragma unroll
            for (int i = 0; i < 8; i++)
                #pragma unroll
                for (int j = 0; j < 4; j++)
                    ffma2(acc[i][j], af[i].y, bf[j].y);
        }

        #pragma unroll
        for (int i = 0; i < 8; i++) {
            const int m = mb * MT_TILE + mt * 8 + i;
            float* orow = g_sim + (size_t)m * N_TR + n0;
            float vmax = -2e30f;
            #pragma unroll
            for (int j = 0; j < 4; j++) {
                const int n = nt + 32 * j;
                if (n0 + n < N_TR) {
                    float lo, hi;
                    asm("mov.b64 {%0,%1}, %2;" : "=f"(lo), "=f"(hi) : "l"(acc[i][j]));
                    const float v = lo + hi;    // even-k + odd-k partial sums
                    orow[n] = v;
                    vmax = fmaxf(vmax, v);
                }
            }
            // warp-wide max over the 128 n-values of this row's block
            #pragma unroll
            for (int o = 16; o; o >>= 1)
                vmax = fmaxf(vmax, __shfl_xor_sync(0xffffffffu, vmax, o));
            if (nt == 0)
                g_blkmax[(size_t)m * NBLK + blockIdx.x] = vmax;
        }
        __syncthreads();
    }
}

// ---------------- top-k helpers ----------------------------------------------
__device__ __forceinline__ void tk_rescan(const float* sv, int base,
                                          float& vmin, int& pmin) {
    float m = sv[base]; int p = base;
    #pragma unroll
    for (int j = 1; j < K_TOP; j++) {
        const float w = sv[base + j];
        if (w < m) { m = w; p = base + j; }
    }
    vmin = m; pmin = p;
}

// Exact top-20 merge across 256 per-thread lists in shared memory.
// WRITE_OUT: write (value, si[]) pairs to g_topv/g_topi for row b.
// Always records the round-19 (20th largest) value into *tau_out (tid 0).
template <bool WRITE_OUT>
__device__ void tk_merge(float* sv, int* si, float* rv, int* rp,
                         int tid, int b, float* tau_out) {
    const int lane = tid & 31, wid = tid >> 5, base = tid * K_TOP;
    for (int r = 0; r < K_TOP; r++) {
        float lv = -3.0f; int lp = base;
        #pragma unroll
        for (int j = 0; j < K_TOP; j++) {
            const float w = sv[base + j];
            if (w > lv) { lv = w; lp = base + j; }
        }
        #pragma unroll
        for (int o = 16; o > 0; o >>= 1) {
            const float ov = __shfl_down_sync(0xffffffffu, lv, o);
            const int   op = __shfl_down_sync(0xffffffffu, lp, o);
            if (ov > lv) { lv = ov; lp = op; }
        }
        if (lane == 0) { rv[wid] = lv; rp[wid] = lp; }
        __syncthreads();
        if (tid == 0) {
            float gv = rv[0]; int gp = rp[0];
            #pragma unroll
            for (int w = 1; w < 8; w++)
                if (rv[w] > gv) { gv = rv[w]; gp = rp[w]; }
            if (WRITE_OUT) {
                g_topv[b * K_TOP + r] = gv;
                g_topi[b * K_TOP + r] = si[gp];
            }
            if (r == K_TOP - 1) *tau_out = gv;
            sv[gp] = -3.0f;   // consume
        }
        __syncthreads();
    }
}

// ---------------- kernel 4: pruned per-row top-20 ----------------------------
// Phase 1: exact top-20 of the 1563 block maxes -> tau (20th largest).
// Since each blockmax is an actual element, true-20th-element >= tau.
// Phase 2: scan ONLY blocks with blockmax >= tau (superset-safe, tie-proof:
// any element e >= true-20th has blockmax >= e >= tau). ~20 blocks x 128.
#define CAND_MAX 96
__global__ void __launch_bounds__(256) k_topk() {
    __shared__ float sv[256 * K_TOP];
    __shared__ int   si[256 * K_TOP];
    __shared__ float rv[8];
    __shared__ int   rp[8];
    __shared__ float s_tau;
    __shared__ int   s_cand[CAND_MAX];
    __shared__ int   s_cnt;
    const int b    = blockIdx.x;
    const int tid  = threadIdx.x;
    const int base = tid * K_TOP;

    // ---- Phase 1: tau from block maxes ----
    #pragma unroll
    for (int j = 0; j < K_TOP; j++) { sv[base + j] = -2.0f; si[base + j] = 0; }
    float vmin = -2.0f; int pmin = base;

    const float* bm = g_blkmax + (size_t)b * NBLK;
    for (int i = tid; i < NBLK; i += 256) {
        const float v = bm[i];
        if (v > vmin) { sv[pmin] = v; si[pmin] = i; tk_rescan(sv, base, vmin, pmin); }
    }
    if (tid == 0) s_cnt = 0;
    __syncthreads();
    tk_merge<false>(sv, si, rv, rp, tid, b, &s_tau);

    // ---- Phase 2: compact candidate blocks, gather, exact top-20 ----
    const float tau = s_tau;
    for (int i = tid; i < NBLK; i += 256) {
        if (bm[i] >= tau) {
            const int p = atomicAdd(&s_cnt, 1);
            if (p < CAND_MAX) s_cand[p] = i;
        }
    }
    #pragma unroll
    for (int j = 0; j < K_TOP; j++) { sv[base + j] = -2.0f; si[base + j] = 0; }
    vmin = -2.0f; pmin = base;
    __syncthreads();

    const int cnt = min(s_cnt, CAND_MAX);
    const float* row = g_sim + (size_t)b * N_TR;
    for (int idx = tid; idx < cnt * NT_TILE; idx += 256) {
        const int blk = s_cand[idx >> 7];
        const int n   = blk * NT_TILE + (idx & 127);
        if (n < N_TR) {
            const float v = __ldg(row + n);
            if (v > vmin) { sv[pmin] = v; si[pmin] = n; tk_rescan(sv, base, vmin, pmin); }
        }
    }
    __syncthreads();
    tk_merge<true>(sv, si, rv, rp, tid, b, &s_tau);
}

// ---------------- kernel 5: zero row + softmax-weighted label scatter -------
// train_y arrives as int32 (jax x64-disabled downcasts the reference's int64).
__global__ void k_out(const int* __restrict__ ty, float* __restrict__ out) {
    const int b = blockIdx.x;
    float* row = out + b * N_CLS;
    for (int i = threadIdx.x; i < N_CLS; i += 256) row[i] = 0.0f;
    __syncthreads();
    if (threadIdx.x < 32) {
        const int j = threadIdx.x;
        const float v = (j < K_TOP) ? g_topv[b * K_TOP + j] : -1e30f;
        float mx = v;
        #pragma unroll
        for (int o = 16; o; o >>= 1) mx = fmaxf(mx, __shfl_xor_sync(0xffffffffu, mx, o));
        const float e = (j < K_TOP) ? expf((v - mx) * TEMP) : 0.0f;
        float s = e;
        #pragma unroll
        for (int o = 16; o; o >>= 1) s += __shfl_xor_sync(0xffffffffu, s, o);
        if (j < K_TOP) {
            const int lab = ty[g_topi[b * K_TOP + j]];
            atomicAdd(row + lab, e / s);
        }
    }
}

// ---------------- launch -----------------------------------------------------
extern "C" void kernel_launch(void* const* d_in, const int* in_sizes, int n_in,
                              void* d_out, int out_size) {
    (void)in_sizes; (void)n_in; (void)out_size;
    const float* x       = (const float*)d_in[0];
    const float* mean    = (const float*)d_in[1];
    const float* inv_std = (const float*)d_in[2];
    const float* tx      = (const float*)d_in[3];
    const int*   ty      = (const int*)d_in[4];
    float* out = (float*)d_out;

    cudaFuncSetAttribute(k_gemm, cudaFuncAttributeMaxDynamicSharedMemorySize,
                         SMEM_BYTES);

    k_qnorm<<<B_Q, 256>>>(x, mean, inv_std);
    k_txinv<<<N_TR / 8, 256>>>(tx);
    k_gemm<<<NBLK, 256, SMEM_BYTES>>>(tx);
    k_topk<<<B_Q, 256>>>();
    k_out<<<B_Q, 256>>>(ty, out);
}

// round 13
// speedup vs baseline: 1.2073x; 1.0012x over previous
#include <cuda_runtime.h>
#include <cstdint>
#include <cstddef>

// Problem constants
#define B_Q   1024
#define D_DIM 256
#define N_TR  200000
#define N_CLS 1000
#define K_TOP 20
#define TEMP  20.0f

// GEMM tiling
#define NT_TILE 128                 // train rows per CTA
#define MT_TILE 64                  // query rows per m-block
#define PITCH   260                 // 256 + 4 pad -> conflict-free LDS.128
#define SMEM_BYTES ((NT_TILE + MT_TILE) * PITCH * 4)
#define NBLK  ((N_TR + NT_TILE - 1) / NT_TILE)   // 1563 n-blocks

// ---------------- device scratch (statically allocated; no cudaMalloc) ------
__device__ __align__(16) float g_q[B_Q * D_DIM];          // normalized queries
__device__ float g_txinv[N_TR];                            // 1/max(||t||,eps)
__device__ __align__(16) float g_sim[(size_t)B_Q * N_TR];  // 819 MB sim matrix
__device__ float g_blkmax[(size_t)B_Q * NBLK];             // per-row block maxes
__device__ float g_topv[B_Q * K_TOP];
__device__ int   g_topi[B_Q * K_TOP];

// ---------------- packed f32x2 FMA ------------------------------------------
__device__ __forceinline__ void ffma2(unsigned long long& c,
                                      unsigned long long a,
                                      unsigned long long b) {
    asm("fma.rn.f32x2 %0, %1, %2, %0;" : "+l"(c) : "l"(a), "l"(b));
}

// ---------------- kernel 1: q = l2norm((x-mean)*inv_std) --------------------
__global__ void k_qnorm(const float* __restrict__ x,
                        const float* __restrict__ mean,
                        const float* __restrict__ inv_std) {
    __shared__ float red[8];
    __shared__ float s_den;
    const int b = blockIdx.x, d = threadIdx.x;
    float t = (x[b * D_DIM + d] - mean[d]) * inv_std[d];
    float ss = t * t;
    #pragma unroll
    for (int o = 16; o; o >>= 1) ss += __shfl_xor_sync(0xffffffffu, ss, o);
    if ((d & 31) == 0) red[d >> 5] = ss;
    __syncthreads();
    if (d == 0) {
        float s = 0.f;
        #pragma unroll
        for (int w = 0; w < 8; w++) s += red[w];
        s_den = fmaxf(sqrtf(s), 1e-8f);
    }
    __syncthreads();
    g_q[b * D_DIM + d] = t / s_den;
}

// ---------------- kernel 2: per-row inverse L2 norm of train bank -----------
__global__ void k_txinv(const float* __restrict__ tx) {
    const int row  = blockIdx.x * 8 + (threadIdx.x >> 5);
    const int lane = threadIdx.x & 31;
    const float4* p = (const float4*)(tx + (size_t)row * D_DIM);
    float4 a = p[lane * 2];
    float4 c = p[lane * 2 + 1];
    float ss = a.x*a.x + a.y*a.y + a.z*a.z + a.w*a.w
             + c.x*c.x + c.y*c.y + c.z*c.z + c.w*c.w;
    #pragma unroll
    for (int o = 16; o; o >>= 1) ss += __shfl_xor_sync(0xffffffffu, ss, o);
    if (lane == 0) g_txinv[row] = 1.0f / fmaxf(sqrtf(ss), 1e-8f);
}

// ---------------- kernel 3: sim = q @ txn^T (fp32 via packed f32x2) ---------
// Epilogue additionally emits the per-(row, n-block) max into g_blkmax for
// the pruned top-k pass. Padded lanes (n >= N_TR) excluded from the max.
__global__ void __launch_bounds__(256, 1) k_gemm(const float* __restrict__ tx) {
    extern __shared__ float sm[];
    float* txs = sm;                       // NT_TILE x PITCH
    float* qs  = sm + NT_TILE * PITCH;     // MT_TILE x PITCH

    const int n0  = blockIdx.x * NT_TILE;
    const int tid = threadIdx.x;

    // Load tx tile once, folding L2 normalization; zero-pad past N_TR.
    for (int idx = tid; idx < NT_TILE * 64; idx += 256) {
        const int r = idx >> 6, c4 = idx & 63;
        const int n = n0 + r;
        float4 v = make_float4(0.f, 0.f, 0.f, 0.f);
        if (n < N_TR) {
            v = __ldg((const float4*)(tx + (size_t)n * D_DIM) + c4);
            const float s = g_txinv[n];
            v.x *= s; v.y *= s; v.z *= s; v.w *= s;
        }
        *(float4*)(txs + r * PITCH + c4 * 4) = v;
    }
    __syncthreads();

    const int nt = tid & 31;   // n-group: warp lanes span all 32
    const int mt = tid >> 5;   // m-group: uniform within a warp (q broadcast)

    for (int mb = 0; mb < B_Q / MT_TILE; mb++) {
        for (int idx = tid; idx < MT_TILE * 64; idx += 256) {
            const int r = idx >> 6, c4 = idx & 63;
            *(float4*)(qs + r * PITCH + c4 * 4) =
                ((const float4*)(g_q + (mb * MT_TILE + r) * D_DIM))[c4];
        }
        __syncthreads();

        unsigned long long acc[8][4];
        #pragma unroll
        for (int i = 0; i < 8; i++)
            #pragma unroll
            for (int j = 0; j < 4; j++) acc[i][j] = 0ULL;  // bits(+0,+0)

        #pragma unroll 2
        for (int k4 = 0; k4 < 64; k4++) {
            ulonglong2 bf[4], af[8];
            #pragma unroll
            for (int j = 0; j < 4; j++)
                bf[j] = *(const ulonglong2*)(txs + (nt + 32 * j) * PITCH + k4 * 4);
            #pragma unroll
            for (int i = 0; i < 8; i++)
                af[i] = *(const ulonglong2*)(qs + (mt * 8 + i) * PITCH + k4 * 4);
            #pragma unroll
            for (int i = 0; i < 8; i++)
                #pragma unroll
                for (int j = 0; j < 4; j++)
                    ffma2(acc[i][j], af[i].x, bf[j].x);
            #pragma unroll
            for (int i = 0; i < 8; i++)
                #pragma unroll
                for (int j = 0; j < 4; j++)
                    ffma2(acc[i][j], af[i].y, bf[j].y);
        }

        #pragma unroll
        for (int i = 0; i < 8; i++) {
            const int m = mb * MT_TILE + mt * 8 + i;
            float* orow = g_sim + (size_t)m * N_TR + n0;
            float vmax = -2e30f;
            #pragma unroll
            for (int j = 0; j < 4; j++) {
                const int n = nt + 32 * j;
                if (n0 + n < N_TR) {
                    float lo, hi;
                    asm("mov.b64 {%0,%1}, %2;" : "=f"(lo), "=f"(hi) : "l"(acc[i][j]));
                    const float v = lo + hi;    // even-k + odd-k partial sums
                    orow[n] = v;
                    vmax = fmaxf(vmax, v);
                }
            }
            // warp-wide max over the 128 n-values of this row's block
            #pragma unroll
            for (int o = 16; o; o >>= 1)
                vmax = fmaxf(vmax, __shfl_xor_sync(0xffffffffu, vmax, o));
            if (nt == 0)
                g_blkmax[(size_t)m * NBLK + blockIdx.x] = vmax;
        }
        __syncthreads();
    }
}

// ---------------- top-k helpers ----------------------------------------------
__device__ __forceinline__ void tk_rescan(const float* sv, int base,
                                          float& vmin, int& pmin) {
    float m = sv[base]; int p = base;
    #pragma unroll
    for (int j = 1; j < K_TOP; j++) {
        const float w = sv[base + j];
        if (w < m) { m = w; p = base + j; }
    }
    vmin = m; pmin = p;
}

// Exact top-20 merge across 256 per-thread lists in shared memory.
// WRITE_OUT: write (value, si[]) pairs to g_topv/g_topi for row b.
// Always records the round-19 (20th largest) value into *tau_out (tid 0).
template <bool WRITE_OUT>
__device__ void tk_merge(float* sv, int* si, float* rv, int* rp,
                         int tid, int b, float* tau_out) {
    const int lane = tid & 31, wid = tid >> 5, base = tid * K_TOP;
    for (int r = 0; r < K_TOP; r++) {
        float lv = -3.0f; int lp = base;
        #pragma unroll
        for (int j = 0; j < K_TOP; j++) {
            const float w = sv[base + j];
            if (w > lv) { lv = w; lp = base + j; }
        }
        #pragma unroll
        for (int o = 16; o > 0; o >>= 1) {
            const float ov = __shfl_down_sync(0xffffffffu, lv, o);
            const int   op = __shfl_down_sync(0xffffffffu, lp, o);
            if (ov > lv) { lv = ov; lp = op; }
        }
        if (lane == 0) { rv[wid] = lv; rp[wid] = lp; }
        __syncthreads();
        if (tid == 0) {
            float gv = rv[0]; int gp = rp[0];
            #pragma unroll
            for (int w = 1; w < 8; w++)
                if (rv[w] > gv) { gv = rv[w]; gp = rp[w]; }
            if (WRITE_OUT) {
                g_topv[b * K_TOP + r] = gv;
                g_topi[b * K_TOP + r] = si[gp];
            }
            if (r == K_TOP - 1) *tau_out = gv;
            sv[gp] = -3.0f;   // consume
        }
        __syncthreads();
    }
}

// ---------------- kernel 4: pruned per-row top-20 ----------------------------
// Phase 1: exact top-20 of the 1563 block maxes -> tau (20th largest).
// Since each blockmax is an actual element, true-20th-element >= tau.
// Phase 2: scan ONLY blocks with blockmax >= tau (superset-safe, tie-proof:
// any element e >= true-20th has blockmax >= e >= tau). ~20 blocks x 128.
#define CAND_MAX 96
__global__ void __launch_bounds__(256) k_topk() {
    __shared__ float sv[256 * K_TOP];
    __shared__ int   si[256 * K_TOP];
    __shared__ float rv[8];
    __shared__ int   rp[8];
    __shared__ float s_tau;
    __shared__ int   s_cand[CAND_MAX];
    __shared__ int   s_cnt;
    const int b    = blockIdx.x;
    const int tid  = threadIdx.x;
    const int base = tid * K_TOP;

    // ---- Phase 1: tau from block maxes ----
    #pragma unroll
    for (int j = 0; j < K_TOP; j++) { sv[base + j] = -2.0f; si[base + j] = 0; }
    float vmin = -2.0f; int pmin = base;

    const float* bm = g_blkmax + (size_t)b * NBLK;
    for (int i = tid; i < NBLK; i += 256) {
        const float v = bm[i];
        if (v > vmin) { sv[pmin] = v; si[pmin] = i; tk_rescan(sv, base, vmin, pmin); }
    }
    if (tid == 0) s_cnt = 0;
    __syncthreads();
    tk_merge<false>(sv, si, rv, rp, tid, b, &s_tau);

    // ---- Phase 2: compact candidate blocks, gather, exact top-20 ----
    const float tau = s_tau;
    for (int i = tid; i < NBLK; i += 256) {
        if (bm[i] >= tau) {
            const int p = atomicAdd(&s_cnt, 1);
            if (p < CAND_MAX) s_cand[p] = i;
        }
    }
    #pragma unroll
    for (int j = 0; j < K_TOP; j++) { sv[base + j] = -2.0f; si[base + j] = 0; }
    vmin = -2.0f; pmin = base;
    __syncthreads();

    const int cnt = min(s_cnt, CAND_MAX);
    const float* row = g_sim + (size_t)b * N_TR;
    for (int idx = tid; idx < cnt * NT_TILE; idx += 256) {
        const int blk = s_cand[idx >> 7];
        const int n   = blk * NT_TILE + (idx & 127);
        if (n < N_TR) {
            const float v = __ldg(row + n);
            if (v > vmin) { sv[pmin] = v; si[pmin] = n; tk_rescan(sv, base, vmin, pmin); }
        }
    }
    __syncthreads();
    tk_merge<true>(sv, si, rv, rp, tid, b, &s_tau);
}

// ---------------- kernel 5: zero row + softmax-weighted label scatter -------
// train_y arrives as int32 (jax x64-disabled downcasts the reference's int64).
__global__ void k_out(const int* __restrict__ ty, float* __restrict__ out) {
    const int b = blockIdx.x;
    float* row = out + b * N_CLS;
    for (int i = threadIdx.x; i < N_CLS; i += 256) row[i] = 0.0f;
    __syncthreads();
    if (threadIdx.x < 32) {
        const int j = threadIdx.x;
        const float v = (j < K_TOP) ? g_topv[b * K_TOP + j] : -1e30f;
        float mx = v;
        #pragma unroll
        for (int o = 16; o; o >>= 1) mx = fmaxf(mx, __shfl_xor_sync(0xffffffffu, mx, o));
        const float e = (j < K_TOP) ? expf((v - mx) * TEMP) : 0.0f;
        float s = e;
        #pragma unroll
        for (int o = 16; o; o >>= 1) s += __shfl_xor_sync(0xffffffffu, s, o);
        if (j < K_TOP) {
            const int lab = ty[g_topi[b * K_TOP + j]];
            atomicAdd(row + lab, e / s);
        }
    }
}

// ---------------- launch -----------------------------------------------------
extern "C" void kernel_launch(void* const* d_in, const int* in_sizes, int n_in,
                              void* d_out, int out_size) {
    (void)in_sizes; (void)n_in; (void)out_size;
    const float* x       = (const float*)d_in[0];
    const float* mean    = (const float*)d_in[1];
    const float* inv_std = (const float*)d_in[2];
    const float* tx      = (const float*)d_in[3];
    const int*   ty      = (const int*)d_in[4];
    float* out = (float*)d_out;

    cudaFuncSetAttribute(k_gemm, cudaFuncAttributeMaxDynamicSharedMemorySize,
                         SMEM_BYTES);

    k_qnorm<<<B_Q, 256>>>(x, mean, inv_std);
    k_txinv<<<N_TR / 8, 256>>>(tx);
    k_gemm<<<NBLK, 256, SMEM_BYTES>>>(tx);
    k_topk<<<B_Q, 256>>>();
    k_out<<<B_Q, 256>>>(ty, out);
}